// round 5
// baseline (speedup 1.0000x reference)
#include <cuda_runtime.h>

typedef unsigned long long ull;

#define MAXB 4096

static __device__ float g_pos[MAXB];
static __device__ float g_part[32 * MAXB];   // [col-tile][row] partial row sums
static __device__ unsigned g_done = 0;

__device__ __forceinline__ void fma2(ull& d, ull a, ull b) {
    asm("fma.rn.f32x2 %0, %1, %2, %0;" : "+l"(d) : "l"(a), "l"(b));
}

__device__ __forceinline__ ull dup2(float v) {
    ull r;
    asm("mov.b64 %0, {%1, %1};" : "=l"(r) : "r"(__float_as_uint(v)));
    return r;
}

// ---------------- SMEM layout (per CTA ~96.5 KB -> 2 CTAs/SM) ----------------
// As: [128 k][64 rows] float, XOR-swizzled (even xor keeps row pairs adjacent) 32 KB
// Bs: [128 k][64 cols] ull (duplicated), XOR-swizzled                          64 KB
// sx2[64], sy2[64], syi[64], rank, red[8]
#define N_A (128 * 64)
#define N_B (128 * 64)

// ---------------- Fused kernel: GEMM + hyperbolic epilogue + norms + final loss ----------------
// Tile: 64 rows (i) x 64 cols (j), 256 threads = 8 warps, 2 CTAs/SM.
// Warp w owns rows w*8..w*8+7 (4 packed pairs); lane l owns cols {l, l+32}.
__global__ void __launch_bounds__(256, 2)
hyp_pair(const float* __restrict__ z, const float* __restrict__ zp,
         float* __restrict__ out, int B) {
    extern __shared__ float smem_f[];
    float* As  = smem_f;                      // 32 KB
    ull*   Bs  = (ull*)(smem_f + N_A);        // 64 KB
    float* sx2 = (float*)(Bs + N_B);          // 64
    float* sy2 = sx2 + 64;                    // 64
    float* syi = sy2 + 64;                    // 64
    unsigned* s_rank = (unsigned*)(syi + 64);
    float*    red    = (float*)(s_rank + 8);  // 8 floats

    const int tid  = threadIdx.x;
    const int lane = tid & 31;
    const int warp = tid >> 5;
    const int row0 = blockIdx.y * 64;
    const int col0 = blockIdx.x * 64;

    // ---- fill A: 64 rows x 128 k (coalesced LDG, swizzled transpose, fused row-norm) ----
    {
        const float4* zA = (const float4*)z + row0 * 32;
        #pragma unroll
        for (int p = 0; p < 8; p++) {
            int r = p * 8 + warp;             // warp owns one full row; lanes sweep k
            float4 v = zA[r * 32 + lane];
            int h = (2 * lane) & 30;          // even XOR swizzle (pairs preserved)
            As[(lane * 4 + 0) * 64 + (r ^ h)] = v.x;
            As[(lane * 4 + 1) * 64 + (r ^ h)] = v.y;
            As[(lane * 4 + 2) * 64 + (r ^ h)] = v.z;
            As[(lane * 4 + 3) * 64 + (r ^ h)] = v.w;
            float s = v.x * v.x + v.y * v.y + v.z * v.z + v.w * v.w;
            #pragma unroll
            for (int o = 16; o; o >>= 1) s += __shfl_xor_sync(0xffffffffu, s, o);
            if (lane == 0) sx2[r] = s;
        }
    }
    // ---- fill B: 64 cols x 128 k (duplicated + swizzled transpose, fused col-norm) ----
    {
        const float4* zB = (const float4*)zp + col0 * 32;
        #pragma unroll
        for (int p = 0; p < 8; p++) {
            int cj = p * 8 + warp;
            float4 v = zB[cj * 32 + lane];
            int g = lane & 15;
            Bs[(lane * 4 + 0) * 64 + (cj ^ g)] = dup2(v.x);
            Bs[(lane * 4 + 1) * 64 + (cj ^ g)] = dup2(v.y);
            Bs[(lane * 4 + 2) * 64 + (cj ^ g)] = dup2(v.z);
            Bs[(lane * 4 + 3) * 64 + (cj ^ g)] = dup2(v.w);
            float s = v.x * v.x + v.y * v.y + v.z * v.z + v.w * v.w;
            #pragma unroll
            for (int o = 16; o; o >>= 1) s += __shfl_xor_sync(0xffffffffu, s, o);
            if (lane == 0) {
                sy2[cj] = s;
                syi[cj] = rsqrtf(fmaxf(s, 1e-24f));   // == 1/max(norm,1e-12)
            }
        }
    }
    __syncthreads();

    ull acc[4][2];
    #pragma unroll
    for (int i = 0; i < 4; i++) {
        acc[i][0] = 0ull; acc[i][1] = 0ull;
    }

    const int rb = warp * 8;
    #pragma unroll 4
    for (int kq = 0; kq < 32; kq++) {
        const int h  = (2 * kq) & 30;
        const int lg = lane ^ (kq & 15);
        #pragma unroll
        for (int s = 0; s < 4; s++) {
            const float* arow = As + (kq * 4 + s) * 64;
            const ull*   brow = Bs + (kq * 4 + s) * 64;
            ull a0 = *(const ull*)(arow + ((rb + 0) ^ h));   // rows rb, rb+1 (broadcast)
            ull a1 = *(const ull*)(arow + ((rb + 2) ^ h));
            ull a2 = *(const ull*)(arow + ((rb + 4) ^ h));
            ull a3 = *(const ull*)(arow + ((rb + 6) ^ h));
            ull b0 = brow[lg];
            ull b1 = brow[lg ^ 32];
            fma2(acc[0][0], a0, b0); fma2(acc[0][1], a0, b1);
            fma2(acc[1][0], a1, b0); fma2(acc[1][1], a1, b1);
            fma2(acc[2][0], a2, b0); fma2(acc[2][1], a2, b1);
            fma2(acc[3][0], a3, b0); fma2(acc[3][1], a3, b1);
        }
    }

    // ---- epilogue: hyperbolic distance + angle sim + exp row-sums ----
    const int cA = lane;                     // (lane ^ (kq&15)) ^ ... b0 col = lane
    const int cB = lane ^ 32;                // careful: b1 col = lane ^ 32 = lane + 32
    float y2v[2], yiv[2];
    y2v[0] = sy2[cA];        yiv[0] = syi[cA];
    y2v[1] = sy2[lane + 32]; yiv[1] = syi[lane + 32];
    (void)cB;

    const float Cc = 0.05f;
    const float SQC = 0.22360679775f;          // sqrt(c)
    #pragma unroll
    for (int rp = 0; rp < 4; rp++) {
        float dv[2][2];
        #pragma unroll
        for (int c = 0; c < 2; c++) {
            unsigned lo, hi;
            asm("mov.b64 {%0, %1}, %2;" : "=r"(lo), "=r"(hi) : "l"(acc[rp][c]));
            dv[0][c] = __uint_as_float(lo);
            dv[1][c] = __uint_as_float(hi);
        }
        #pragma unroll
        for (int hh = 0; hh < 2; hh++) {
            int li = rb + rp * 2 + hh;
            int gi = row0 + li;
            float x2  = sx2[li];
            float xin = rsqrtf(fmaxf(x2, 1e-24f));
            float B1 = 1.0f - Cc * x2;
            float s = 0.0f;
            #pragma unroll
            for (int c = 0; c < 2; c++) {
                int gj = col0 + lane + 32 * c;
                float d  = dv[hh][c];                 // <z_i, z'_j>
                float y2 = y2v[c];
                float A1  = 1.0f + Cc * (y2 - 2.0f * d);
                float den = fmaxf(1.0f - 2.0f * Cc * d + Cc * Cc * x2 * y2, 1e-6f);
                float num = fmaxf(A1 * A1 * x2 - 2.0f * A1 * B1 * d + B1 * B1 * y2, 0.0f);
                float mn  = num * rsqrtf(fmaxf(num, 1e-37f));     // sqrt(num)
                float u   = fminf(__fdividef(SQC * mn, den), 1.0f - 1e-6f);
                float lgr = __logf(__fdividef(1.0f + u, 1.0f - u)); // 2*atanh(u)
                float cosv = d * xin * yiv[c];
                // combined = 0.5*(-dist/T) + 0.5*cos/T ; dist = (1/sqrt(c))*lgr
                float comb = 5.0f * cosv - 22.360679775f * lgr;
                if (gi == gj) g_pos[gi] = comb;       // diagonal -> pos_sim
                else          s += __expf(comb);      // off-diagonal -> denom
            }
            #pragma unroll
            for (int o = 16; o; o >>= 1) s += __shfl_xor_sync(0xffffffffu, s, o);
            if (lane == 0) g_part[blockIdx.x * MAXB + gi] = s;   // deterministic partials
        }
    }

    // ---- last CTA to finish performs the final reduction (deterministic) ----
    __syncthreads();
    __threadfence();
    if (tid == 0) *s_rank = atomicAdd(&g_done, 1u);
    __syncthreads();
    unsigned nblk = gridDim.x * gridDim.y;
    if (*s_rank == nblk - 1) {
        int nparts = gridDim.x;
        float s = 0.0f;
        for (int i = tid; i < B; i += 256) {
            float dsum = 0.0f;
            #pragma unroll 4
            for (int p = 0; p < nparts; p++) dsum += g_part[p * MAXB + i];
            s += __logf(dsum) - g_pos[i];
        }
        #pragma unroll
        for (int o = 16; o; o >>= 1) s += __shfl_xor_sync(0xffffffffu, s, o);
        if (lane == 0) red[warp] = s;
        __syncthreads();
        if (tid == 0) {
            float tot = 0.0f;
            #pragma unroll
            for (int w = 0; w < 8; w++) tot += red[w];
            out[0] = tot / (float)B;
            g_done = 0;                         // reset for next graph replay
        }
    }
}

extern "C" void kernel_launch(void* const* d_in, const int* in_sizes, int n_in,
                              void* d_out, int out_size) {
    (void)n_in; (void)out_size;
    const float* z  = (const float*)d_in[0];
    const float* zp = (const float*)d_in[1];
    int B = in_sizes[0] / 128;

    int smem = N_A * (int)sizeof(float) + N_B * (int)sizeof(ull)
             + 256 * (int)sizeof(float);                        // ~97.25 KB
    cudaFuncSetAttribute(hyp_pair, cudaFuncAttributeMaxDynamicSharedMemorySize, smem);
    dim3 grid(B / 64, B / 64);
    hyp_pair<<<grid, 256, smem>>>(z, zp, (float*)d_out, B);
}

// round 6
// speedup vs baseline: 1.1875x; 1.1875x over previous
#include <cuda_runtime.h>

typedef unsigned long long ull;

#define MAXB 4096

static __device__ float g_pos[MAXB];
static __device__ float g_part[32 * MAXB];   // [part = colTile*2 + half][row]
static __device__ unsigned g_done = 0;

__device__ __forceinline__ void fma2(ull& d, ull a, ull b) {
    asm("fma.rn.f32x2 %0, %1, %2, %0;" : "+l"(d) : "l"(a), "l"(b));
}

__device__ __forceinline__ ull dup2(float v) {
    ull r;
    asm("mov.b64 %0, {%1, %1};" : "=l"(r) : "r"(__float_as_uint(v)));
    return r;
}

#define N_A (128 * 64)     // A: [k][64 rows] float, XOR-swizzled  (32 KB)
#define N_B (128 * 128)    // B: [k][128 cols] ull duplicated      (128 KB)

// ---------------- Fused kernel ----------------
// Tile 64 rows x 128 cols, 512 threads = 16 warps, 128 CTAs (grid 8 x 16).
// k-split: warps 0-7 do k=0..63, warps 8-15 do k=64..127, same outputs.
// Warp pair (w, w+8): rows (w&7)*8..+7; lane l cols {l,l+32,l+64,l+96}.
// After mainloop, halves are exchanged via smem (A region) and the epilogue
// is split: warp w -> cols {l,l+32}, warp w+8 -> cols {l+64,l+96}.
__global__ void __launch_bounds__(512, 1)
hyp_pair(const float* __restrict__ z, const float* __restrict__ zp,
         float* __restrict__ out, int B) {
    extern __shared__ float smem_f[];
    float* As  = smem_f;                      // 32 KB (reused as exchange buffer)
    ull*   Bs  = (ull*)(smem_f + N_A);        // 128 KB
    float* sx2 = (float*)(Bs + N_B);          // 64
    float* sy2 = sx2 + 64;                    // 128
    float* syi = sy2 + 128;                   // 128
    unsigned* s_rank = (unsigned*)(syi + 128);
    float*    red    = (float*)(s_rank + 8);  // 16 floats

    const int tid  = threadIdx.x;
    const int lane = tid & 31;
    const int warp = tid >> 5;
    const int wlo  = warp & 7;                // row-group id
    const int khalf = warp >> 3;              // 0: k=0..63, 1: k=64..127
    const int row0 = blockIdx.y * 64;
    const int col0 = blockIdx.x * 128;

    // ---- fill A: 64 rows x 128 k (coalesced, swizzled transpose, fused row-norm) ----
    {
        const float4* zA = (const float4*)z + row0 * 32;
        #pragma unroll
        for (int p = 0; p < 4; p++) {
            int r = p * 16 + warp;            // warp owns a full row; lanes sweep k
            float4 v = zA[r * 32 + lane];
            int h = (2 * lane) & 30;          // even XOR swizzle (row pairs preserved)
            As[(lane * 4 + 0) * 64 + (r ^ h)] = v.x;
            As[(lane * 4 + 1) * 64 + (r ^ h)] = v.y;
            As[(lane * 4 + 2) * 64 + (r ^ h)] = v.z;
            As[(lane * 4 + 3) * 64 + (r ^ h)] = v.w;
            float s = v.x * v.x + v.y * v.y + v.z * v.z + v.w * v.w;
            #pragma unroll
            for (int o = 16; o; o >>= 1) s += __shfl_xor_sync(0xffffffffu, s, o);
            if (lane == 0) sx2[r] = s;
        }
    }
    // ---- fill B: 128 cols x 128 k (duplicated, swizzled transpose, fused col-norm) ----
    {
        const float4* zB = (const float4*)zp + col0 * 32;
        #pragma unroll
        for (int p = 0; p < 8; p++) {
            int cj = p * 16 + warp;
            float4 v = zB[cj * 32 + lane];
            int g = lane & 15;
            Bs[(lane * 4 + 0) * 128 + (cj ^ g)] = dup2(v.x);
            Bs[(lane * 4 + 1) * 128 + (cj ^ g)] = dup2(v.y);
            Bs[(lane * 4 + 2) * 128 + (cj ^ g)] = dup2(v.z);
            Bs[(lane * 4 + 3) * 128 + (cj ^ g)] = dup2(v.w);
            float s = v.x * v.x + v.y * v.y + v.z * v.z + v.w * v.w;
            #pragma unroll
            for (int o = 16; o; o >>= 1) s += __shfl_xor_sync(0xffffffffu, s, o);
            if (lane == 0) {
                sy2[cj] = s;
                syi[cj] = rsqrtf(fmaxf(s, 1e-24f));   // == 1/max(norm,1e-12)
            }
        }
    }
    __syncthreads();

    ull acc[4][4];
    #pragma unroll
    for (int i = 0; i < 4; i++)
        #pragma unroll
        for (int j = 0; j < 4; j++) acc[i][j] = 0ull;

    const int rb = wlo * 8;
    const int kq0 = khalf * 16;
    #pragma unroll 2
    for (int kk = 0; kk < 16; kk++) {
        const int kq = kq0 + kk;
        const int h  = (2 * kq) & 30;
        const int lg = lane ^ (kq & 15);
        #pragma unroll
        for (int s = 0; s < 4; s++) {
            const float* arow = As + (kq * 4 + s) * 64;
            const ull*   brow = Bs + (kq * 4 + s) * 128;
            ull a0 = *(const ull*)(arow + ((rb + 0) ^ h));   // rows rb, rb+1 (broadcast)
            ull a1 = *(const ull*)(arow + ((rb + 2) ^ h));
            ull a2 = *(const ull*)(arow + ((rb + 4) ^ h));
            ull a3 = *(const ull*)(arow + ((rb + 6) ^ h));
            ull b0 = brow[lg];
            ull b1 = brow[lg + 32];
            ull b2 = brow[lg + 64];
            ull b3 = brow[lg + 96];
            fma2(acc[0][0], a0, b0); fma2(acc[0][1], a0, b1);
            fma2(acc[0][2], a0, b2); fma2(acc[0][3], a0, b3);
            fma2(acc[1][0], a1, b0); fma2(acc[1][1], a1, b1);
            fma2(acc[1][2], a1, b2); fma2(acc[1][3], a1, b3);
            fma2(acc[2][0], a2, b0); fma2(acc[2][1], a2, b1);
            fma2(acc[2][2], a2, b2); fma2(acc[2][3], a2, b3);
            fma2(acc[3][0], a3, b0); fma2(acc[3][1], a3, b1);
            fma2(acc[3][2], a3, b2); fma2(acc[3][3], a3, b3);
        }
    }

    // ---- exchange partial-k accumulators through smem (A region is dead) ----
    // layout: xb[idx][wlo][lane], idx 0..15 -> conflict-free (lane-contiguous)
    __syncthreads();                          // all mainloop reads of As done
    {
        ull* xb = (ull*)As;                   // 4096 ull = 32 KB exactly
        if (khalf == 0) {                     // give away cols {l+64, l+96}
            #pragma unroll
            for (int rp = 0; rp < 4; rp++) {
                xb[(8 + rp * 2 + 0) * 256 + wlo * 32 + lane] = acc[rp][2];
                xb[(8 + rp * 2 + 1) * 256 + wlo * 32 + lane] = acc[rp][3];
            }
        } else {                              // give away cols {l, l+32}
            #pragma unroll
            for (int rp = 0; rp < 4; rp++) {
                xb[(rp * 2 + 0) * 256 + wlo * 32 + lane] = acc[rp][0];
                xb[(rp * 2 + 1) * 256 + wlo * 32 + lane] = acc[rp][1];
            }
        }
        __syncthreads();
        const ull ONE2 = dup2(1.0f);
        if (khalf == 0) {                     // keep cols {l, l+32}
            #pragma unroll
            for (int rp = 0; rp < 4; rp++) {
                fma2(acc[rp][0], xb[(rp * 2 + 0) * 256 + wlo * 32 + lane], ONE2);
                fma2(acc[rp][1], xb[(rp * 2 + 1) * 256 + wlo * 32 + lane], ONE2);
            }
        } else {                              // keep cols {l+64, l+96}
            #pragma unroll
            for (int rp = 0; rp < 4; rp++) {
                fma2(acc[rp][2], xb[(8 + rp * 2 + 0) * 256 + wlo * 32 + lane], ONE2);
                fma2(acc[rp][3], xb[(8 + rp * 2 + 1) * 256 + wlo * 32 + lane], ONE2);
            }
        }
    }

    // ---- epilogue: warp handles cols khalf*64 + {lane, lane+32} ----
    {
        const int c0 = khalf * 2;             // acc col index base (0 or 2)
        const int cb = khalf * 64;            // column offset base
        float y2v[2], yiv[2];
        y2v[0] = sy2[cb + lane];        yiv[0] = syi[cb + lane];
        y2v[1] = sy2[cb + lane + 32];   yiv[1] = syi[cb + lane + 32];

        const float Cc = 0.05f;
        const float SQC = 0.22360679775f;     // sqrt(c)
        #pragma unroll
        for (int rp = 0; rp < 4; rp++) {
            float dv[2][2];
            #pragma unroll
            for (int c = 0; c < 2; c++) {
                unsigned lo, hi;
                asm("mov.b64 {%0, %1}, %2;" : "=r"(lo), "=r"(hi) : "l"(acc[rp][c0 + c]));
                dv[0][c] = __uint_as_float(lo);
                dv[1][c] = __uint_as_float(hi);
            }
            #pragma unroll
            for (int hh = 0; hh < 2; hh++) {
                int li = rb + rp * 2 + hh;
                int gi = row0 + li;
                float x2  = sx2[li];
                float xin = rsqrtf(fmaxf(x2, 1e-24f));
                float B1 = 1.0f - Cc * x2;
                float s = 0.0f;
                #pragma unroll
                for (int c = 0; c < 2; c++) {
                    int gj = col0 + cb + lane + 32 * c;
                    float d  = dv[hh][c];                 // <z_i, z'_j>
                    float y2 = y2v[c];
                    float A1  = 1.0f + Cc * (y2 - 2.0f * d);
                    float den = fmaxf(1.0f - 2.0f * Cc * d + Cc * Cc * x2 * y2, 1e-6f);
                    float num = fmaxf(A1 * A1 * x2 - 2.0f * A1 * B1 * d + B1 * B1 * y2, 0.0f);
                    float mn  = num * rsqrtf(fmaxf(num, 1e-37f));   // sqrt(num)
                    float t   = SQC * mn;
                    float pn  = den + t;
                    float qn  = fmaxf(den - t, 1e-6f * den);        // == u <= 1-1e-6 guard
                    float l2  = __log2f(pn) - __log2f(qn);          // log2((1+u)/(1-u))
                    float cosv = d * xin * yiv[c];
                    if (gi == gj) {
                        g_pos[gi] = 5.0f * cosv - 15.4993876f * l2; // natural-log comb
                    } else {
                        s += exp2f(7.21347520f * cosv - 22.3606798f * l2);
                    }
                }
                #pragma unroll
                for (int o = 16; o; o >>= 1) s += __shfl_xor_sync(0xffffffffu, s, o);
                if (lane == 0) g_part[(blockIdx.x * 2 + khalf) * MAXB + gi] = s;
            }
        }
    }

    // ---- last CTA performs final reduction (deterministic) ----
    __syncthreads();
    __threadfence();
    if (tid == 0) *s_rank = atomicAdd(&g_done, 1u);
    __syncthreads();
    unsigned nblk = gridDim.x * gridDim.y;
    if (*s_rank == nblk - 1) {
        int nparts = gridDim.x * 2;
        float s = 0.0f;
        for (int i = tid; i < B; i += 512) {
            float dsum = 0.0f;
            #pragma unroll 4
            for (int p = 0; p < nparts; p++) dsum += g_part[p * MAXB + i];
            s += __logf(dsum) - g_pos[i];
        }
        #pragma unroll
        for (int o = 16; o; o >>= 1) s += __shfl_xor_sync(0xffffffffu, s, o);
        if (lane == 0) red[warp] = s;
        __syncthreads();
        if (tid == 0) {
            float tot = 0.0f;
            #pragma unroll
            for (int w = 0; w < 16; w++) tot += red[w];
            out[0] = tot / (float)B;
            g_done = 0;                         // reset for next graph replay
        }
    }
}

extern "C" void kernel_launch(void* const* d_in, const int* in_sizes, int n_in,
                              void* d_out, int out_size) {
    (void)n_in; (void)out_size;
    const float* z  = (const float*)d_in[0];
    const float* zp = (const float*)d_in[1];
    int B = in_sizes[0] / 128;

    int smem = N_A * (int)sizeof(float) + N_B * (int)sizeof(ull)
             + 512 * (int)sizeof(float);                        // ~162 KB
    cudaFuncSetAttribute(hyp_pair, cudaFuncAttributeMaxDynamicSharedMemorySize, smem);
    dim3 grid(B / 128, B / 64);
    hyp_pair<<<grid, 512, smem>>>(z, zp, (float*)d_out, B);
}

// round 7
// speedup vs baseline: 1.6193x; 1.3636x over previous
#include <cuda_runtime.h>

typedef unsigned long long ull;

#define MAXB 4096

static __device__ float g_pos[MAXB];
static __device__ float g_part[32 * MAXB];   // [col-tile][row] partial row sums
static __device__ unsigned g_done = 0;

__device__ __forceinline__ void fma2(ull& d, ull a, ull b) {
    asm("fma.rn.f32x2 %0, %1, %2, %0;" : "+l"(d) : "l"(a), "l"(b));
}

__device__ __forceinline__ ull dup2(float v) {
    ull r;
    asm("mov.b64 %0, {%1, %1};" : "=l"(r) : "r"(__float_as_uint(v)));
    return r;
}

#define N_A (128 * 64)     // A: [k][64 rows] float, even-XOR swizzle (32 KB)
#define N_B (128 * 128)    // B: [k][128 cols] float, col-quad swizzle (64 KB)

// ---------------- Fused kernel ----------------
// Tile 64 rows x 128 cols, 256 threads = 8 warps, grid (B/128, B/64) = 128 CTAs.
// Warp w: rows w*8..w*8+7. Lane l: cols 4l..4l+3.
// Thread micro-tile: 8 rows x 4 cols = 16 packed-pair accumulators.
// A smem: [k][64] floats, row index swizzled r^h, h=(2*(k>>2))&30 (pairs intact).
// B smem: [k][128] floats, col index swizzled c^s, s=((k>>2)&7)<<2 (quads intact).
__global__ void __launch_bounds__(256, 1)
hyp_pair(const float* __restrict__ z, const float* __restrict__ zp,
         float* __restrict__ out, int B) {
    extern __shared__ float smem_f[];
    float* As  = smem_f;                      // 32 KB
    float* Bs  = smem_f + N_A;                // 64 KB
    float* sx2 = Bs + N_B;                    // 64
    float* sy2 = sx2 + 64;                    // 128
    float* syi = sy2 + 128;                   // 128
    unsigned* s_rank = (unsigned*)(syi + 128);
    float*    red    = (float*)(s_rank + 8);  // 8 floats

    const int tid  = threadIdx.x;
    const int lane = tid & 31;
    const int warp = tid >> 5;
    const int row0 = blockIdx.y * 64;
    const int col0 = blockIdx.x * 128;

    // ---- fill A: 64 rows x 128 k (coalesced LDG, swizzled transpose, fused row-norm) ----
    {
        const float4* zA = (const float4*)z + row0 * 32;
        #pragma unroll
        for (int p = 0; p < 8; p++) {
            int r = p * 8 + warp;             // warp owns one full row; lanes sweep k-quads
            float4 v = zA[r * 32 + lane];
            int h = (2 * lane) & 30;          // kq = lane
            As[(lane * 4 + 0) * 64 + (r ^ h)] = v.x;
            As[(lane * 4 + 1) * 64 + (r ^ h)] = v.y;
            As[(lane * 4 + 2) * 64 + (r ^ h)] = v.z;
            As[(lane * 4 + 3) * 64 + (r ^ h)] = v.w;
            float s = v.x * v.x + v.y * v.y + v.z * v.z + v.w * v.w;
            #pragma unroll
            for (int o = 16; o; o >>= 1) s += __shfl_xor_sync(0xffffffffu, s, o);
            if (lane == 0) sx2[r] = s;
        }
    }
    // ---- fill B: 128 cols x 128 k (swizzled transpose, fused col-norm) ----
    {
        const float4* zB = (const float4*)zp + col0 * 32;
        #pragma unroll
        for (int p = 0; p < 16; p++) {
            int cj = p * 8 + warp;
            float4 v = zB[cj * 32 + lane];
            int sswz = (lane & 7) << 2;       // kq = lane -> s = ((k>>2)&7)<<2
            Bs[(lane * 4 + 0) * 128 + (cj ^ sswz)] = v.x;
            Bs[(lane * 4 + 1) * 128 + (cj ^ sswz)] = v.y;
            Bs[(lane * 4 + 2) * 128 + (cj ^ sswz)] = v.z;
            Bs[(lane * 4 + 3) * 128 + (cj ^ sswz)] = v.w;
            float s = v.x * v.x + v.y * v.y + v.z * v.z + v.w * v.w;
            #pragma unroll
            for (int o = 16; o; o >>= 1) s += __shfl_xor_sync(0xffffffffu, s, o);
            if (lane == 0) {
                sy2[cj] = s;
                syi[cj] = rsqrtf(fmaxf(s, 1e-24f));   // == 1/max(norm,1e-12)
            }
        }
    }
    __syncthreads();

    ull acc[4][4];                            // [row-pair][col]
    #pragma unroll
    for (int i = 0; i < 4; i++)
        #pragma unroll
        for (int j = 0; j < 4; j++) acc[i][j] = 0ull;

    const int rb   = warp * 8;
    const int bcol = lane * 4;
    #pragma unroll 4
    for (int kq = 0; kq < 32; kq++) {
        const int h    = (2 * kq) & 30;
        const int sswz = (kq & 7) << 2;
        const float* arow = As + kq * 256;    // 4 k's x 64
        const float* brow = Bs + kq * 512 + (bcol ^ sswz);
        #pragma unroll
        for (int j = 0; j < 4; j++) {
            const float* ar = arow + j * 64;
            ull a0 = *(const ull*)(ar + ((rb + 0) ^ h));   // broadcast row pairs
            ull a1 = *(const ull*)(ar + ((rb + 2) ^ h));
            ull a2 = *(const ull*)(ar + ((rb + 4) ^ h));
            ull a3 = *(const ull*)(ar + ((rb + 6) ^ h));
            float4 bv = *(const float4*)(brow + j * 128);  // cols 4l..4l+3
            ull b0 = dup2(bv.x);
            ull b1 = dup2(bv.y);
            ull b2 = dup2(bv.z);
            ull b3 = dup2(bv.w);
            fma2(acc[0][0], a0, b0); fma2(acc[0][1], a0, b1);
            fma2(acc[0][2], a0, b2); fma2(acc[0][3], a0, b3);
            fma2(acc[1][0], a1, b0); fma2(acc[1][1], a1, b1);
            fma2(acc[1][2], a1, b2); fma2(acc[1][3], a1, b3);
            fma2(acc[2][0], a2, b0); fma2(acc[2][1], a2, b1);
            fma2(acc[2][2], a2, b2); fma2(acc[2][3], a2, b3);
            fma2(acc[3][0], a3, b0); fma2(acc[3][1], a3, b1);
            fma2(acc[3][2], a3, b2); fma2(acc[3][3], a3, b3);
        }
    }

    // ---- epilogue: thread owns rows rb..rb+7, cols col0+4*lane..+3 ----
    {
        float y2v[4], yiv[4];
        #pragma unroll
        for (int c = 0; c < 4; c++) {
            y2v[c] = sy2[bcol + c];
            yiv[c] = syi[bcol + c];
        }
        const float Cc = 0.05f;
        const float SQC = 0.22360679775f;     // sqrt(c)
        #pragma unroll
        for (int rp = 0; rp < 4; rp++) {
            float dv[2][4];
            #pragma unroll
            for (int c = 0; c < 4; c++) {
                unsigned lo, hi;
                asm("mov.b64 {%0, %1}, %2;" : "=r"(lo), "=r"(hi) : "l"(acc[rp][c]));
                dv[0][c] = __uint_as_float(lo);
                dv[1][c] = __uint_as_float(hi);
            }
            #pragma unroll
            for (int hh = 0; hh < 2; hh++) {
                int li = rb + rp * 2 + hh;
                int gi = row0 + li;
                float x2  = sx2[li];
                float xin = rsqrtf(fmaxf(x2, 1e-24f));
                float B1 = 1.0f - Cc * x2;
                float s = 0.0f;
                #pragma unroll
                for (int c = 0; c < 4; c++) {
                    int gj = col0 + bcol + c;
                    float d  = dv[hh][c];                 // <z_i, z'_j>
                    float y2 = y2v[c];
                    float A1  = 1.0f + Cc * (y2 - 2.0f * d);
                    float den = fmaxf(1.0f - 2.0f * Cc * d + Cc * Cc * x2 * y2, 1e-6f);
                    float num = fmaxf(A1 * A1 * x2 - 2.0f * A1 * B1 * d + B1 * B1 * y2, 0.0f);
                    float mn  = num * rsqrtf(fmaxf(num, 1e-37f));   // sqrt(num)
                    float t   = SQC * mn;
                    float pn  = den + t;
                    float qn  = fmaxf(den - t, 1e-6f * den);        // u <= 1-1e-6 guard
                    float l2  = __log2f(pn) - __log2f(qn);          // log2((1+u)/(1-u))
                    float cosv = d * xin * yiv[c];
                    if (gi == gj) {
                        g_pos[gi] = 5.0f * cosv - 15.4993876f * l2; // 22.3607*ln2
                    } else {
                        s += exp2f(7.21347520f * cosv - 22.3606798f * l2);
                    }
                }
                #pragma unroll
                for (int o = 16; o; o >>= 1) s += __shfl_xor_sync(0xffffffffu, s, o);
                if (lane == 0) g_part[blockIdx.x * MAXB + gi] = s;
            }
        }
    }

    // ---- last CTA performs the final reduction (deterministic) ----
    __syncthreads();
    __threadfence();
    if (tid == 0) *s_rank = atomicAdd(&g_done, 1u);
    __syncthreads();
    unsigned nblk = gridDim.x * gridDim.y;
    if (*s_rank == nblk - 1) {
        int nparts = gridDim.x;
        float s = 0.0f;
        for (int i = tid; i < B; i += 256) {
            float dsum = 0.0f;
            #pragma unroll
            for (int p = 0; p < 8; p++) dsum += g_part[p * MAXB + i];
            s += __logf(dsum) - g_pos[i];
        }
        #pragma unroll
        for (int o = 16; o; o >>= 1) s += __shfl_xor_sync(0xffffffffu, s, o);
        if (lane == 0) red[warp] = s;
        __syncthreads();
        if (tid == 0) {
            float tot = 0.0f;
            #pragma unroll
            for (int w = 0; w < 8; w++) tot += red[w];
            out[0] = tot / (float)B;
            g_done = 0;                         // reset for next graph replay
        }
    }
}

extern "C" void kernel_launch(void* const* d_in, const int* in_sizes, int n_in,
                              void* d_out, int out_size) {
    (void)n_in; (void)out_size;
    const float* z  = (const float*)d_in[0];
    const float* zp = (const float*)d_in[1];
    int B = in_sizes[0] / 128;

    int smem = (N_A + N_B) * (int)sizeof(float) + 384 * (int)sizeof(float); // ~97.5 KB
    cudaFuncSetAttribute(hyp_pair, cudaFuncAttributeMaxDynamicSharedMemorySize, smem);
    dim3 grid(B / 128, B / 64);
    hyp_pair<<<grid, 256, smem>>>(z, zp, (float*)d_out, B);
}